// round 2
// baseline (speedup 1.0000x reference)
#include <cuda_runtime.h>
#include <cstdint>

#define N_NODES 50000
#define N_EDGES 400000
#define D_IN    128
#define HID     256
#define BN_EPS  1e-5f

// ---------------- scratch (static __device__ globals: allocation-free) -------
__device__ int   g_is64;
__device__ int   g_deg_f[N_NODES];
__device__ int   g_deg_b[N_NODES];
__device__ int   g_off_f[N_NODES + 1];
__device__ int   g_off_b[N_NODES + 1];
__device__ int   g_cur_f[N_NODES];
__device__ int   g_cur_b[N_NODES];
__device__ int   g_adj_f[N_EDGES];   // for node i (as dst): list of src
__device__ int   g_adj_b[N_EDGES];   // for node i (as src): list of dst
__device__ __align__(16) float g_mean_f[(size_t)N_NODES * HID];
__device__ __align__(16) float g_mean_b[(size_t)N_NODES * HID];
__device__ __align__(16) float g_h1[(size_t)N_NODES * HID];
__device__ __align__(16) float g_h2[(size_t)N_NODES * HID];
__device__ float g_stats[2 * HID];   // [sum, sumsq]

// ---------------- edge dtype detection ---------------------------------------
// edge_index may be int32 (JAX default, x64 disabled) or int64. Interpreted as
// int32 pairs, int64 data has hi-word == 0 for every element (all values in
// [0, 50000)). For int32 data the "hi" slot is a real random index, nonzero
// with prob ~1-2e-5 — 256 consecutive zeros cannot happen.
__global__ void k_detect(const int* __restrict__ ei32) {
    if (threadIdx.x == 0) {
        int is64 = 1;
        for (int i = 0; i < 256; i++) {
            if (ei32[2 * i + 1] != 0) { is64 = 0; break; }
        }
        g_is64 = is64;
    }
}

__device__ __forceinline__ void load_edge(const int* ei32, int i, int& s, int& d) {
    if (g_is64) {
        s = ei32[2 * i];
        d = ei32[2 * (N_EDGES + i)];
    } else {
        s = ei32[i];
        d = ei32[N_EDGES + i];
    }
}

// ---------------- graph build ------------------------------------------------
__global__ void k_zero_deg() {
    int i = blockIdx.x * blockDim.x + threadIdx.x;
    if (i < N_NODES) { g_deg_f[i] = 0; g_deg_b[i] = 0; }
}

__global__ void k_count(const int* __restrict__ ei32) {
    int i = blockIdx.x * blockDim.x + threadIdx.x;
    if (i < N_EDGES) {
        int s, d;
        load_edge(ei32, i, s, d);
        if ((unsigned)s < N_NODES && (unsigned)d < N_NODES) {
            atomicAdd(&g_deg_b[s], 1);
            atomicAdd(&g_deg_f[d], 1);
        }
    }
}

// single-block exclusive scan of both degree arrays
__global__ void k_scan() {
    __shared__ int sh[1024];
    for (int pass = 0; pass < 2; pass++) {
        const int* deg = pass ? g_deg_b : g_deg_f;
        int* off = pass ? g_off_b : g_off_f;
        int* cur = pass ? g_cur_b : g_cur_f;
        int carry = 0;
        for (int base = 0; base < N_NODES; base += 1024) {
            int i = base + threadIdx.x;
            int v = (i < N_NODES) ? deg[i] : 0;
            sh[threadIdx.x] = v;
            __syncthreads();
            for (int o = 1; o < 1024; o <<= 1) {
                int t = (threadIdx.x >= o) ? sh[threadIdx.x - o] : 0;
                __syncthreads();
                sh[threadIdx.x] += t;
                __syncthreads();
            }
            int incl = sh[threadIdx.x];
            int tot = sh[1023];
            if (i < N_NODES) {
                int ex = carry + incl - v;
                off[i] = ex;
                cur[i] = ex;
            }
            carry += tot;
            __syncthreads();
        }
        if (threadIdx.x == 0) off[N_NODES] = carry;
        __syncthreads();
    }
}

__global__ void k_scatter(const int* __restrict__ ei32) {
    int i = blockIdx.x * blockDim.x + threadIdx.x;
    if (i < N_EDGES) {
        int s, d;
        load_edge(ei32, i, s, d);
        if ((unsigned)s < N_NODES && (unsigned)d < N_NODES) {
            int p = atomicAdd(&g_cur_f[d], 1); g_adj_f[p] = s;
            int q = atomicAdd(&g_cur_b[s], 1); g_adj_b[q] = d;
        }
    }
}

// ---------------- aggregation: one warp per node, mean of neighbor features --
// dir: 0 = fwd (aggregate into dst), 1 = bwd. use_h1: feature source.
template <int D>
__global__ void k_agg(const float* __restrict__ x, int dir, int use_h1) {
    int warp = (blockIdx.x * blockDim.x + threadIdx.x) >> 5;
    int lane = threadIdx.x & 31;
    if (warp >= N_NODES) return;
    const float* feat = use_h1 ? g_h1 : x;
    const int* off = dir ? g_off_b : g_off_f;
    const int* adj = dir ? g_adj_b : g_adj_f;
    float* out = dir ? g_mean_b : g_mean_f;

    int s = off[warp], e = off[warp + 1];
    float4 a0 = make_float4(0.f, 0.f, 0.f, 0.f);
    float4 a1 = make_float4(0.f, 0.f, 0.f, 0.f);
    for (int j = s; j < e; j++) {
        int nb = adj[j];
        const float4* p = reinterpret_cast<const float4*>(feat + (size_t)nb * D);
        float4 v = p[lane];
        a0.x += v.x; a0.y += v.y; a0.z += v.z; a0.w += v.w;
        if (D == 256) {
            float4 w = p[lane + 32];
            a1.x += w.x; a1.y += w.y; a1.z += w.z; a1.w += w.w;
        }
    }
    int cnt = e - s;
    float inv = 1.0f / (float)(cnt > 0 ? cnt : 1);
    a0.x *= inv; a0.y *= inv; a0.z *= inv; a0.w *= inv;
    float4* q = reinterpret_cast<float4*>(out + (size_t)warp * D);
    q[lane] = a0;
    if (D == 256) {
        a1.x *= inv; a1.y *= inv; a1.z *= inv; a1.w *= inv;
        q[lane + 32] = a1;
    }
}

// ---------------- fused 3-segment GEMM: C = A1@W1 + A2@W2 + A3@(W3a+W3b) + (ba+bb)
#define BM 128
#define BN 64
#define BK 16

__global__ __launch_bounds__(256)
void k_gemm3(const float* __restrict__ x,
             const float* __restrict__ W1, const float* __restrict__ W2,
             const float* __restrict__ W3a, const float* __restrict__ W3b,
             const float* __restrict__ ba, const float* __restrict__ bb,
             int K, int layer) {
    __shared__ float As[BK][BM];
    __shared__ float Bs[BK][BN];

    const float* A1 = g_mean_f;
    const float* A2 = g_mean_b;
    const float* A3 = layer ? g_h1 : x;
    float* C = layer ? g_h2 : g_h1;

    int tid = threadIdx.x;
    int m0 = blockIdx.x * BM;
    int n0 = blockIdx.y * BN;
    int tx = tid & 15;   // n dim: 4 cols
    int ty = tid >> 4;   // m dim: 8 rows

    float acc[8][4];
#pragma unroll
    for (int i = 0; i < 8; i++)
#pragma unroll
        for (int j = 0; j < 4; j++) acc[i][j] = 0.f;

    for (int seg = 0; seg < 3; seg++) {
        const float* A = (seg == 0) ? A1 : (seg == 1) ? A2 : A3;
        const float* W = (seg == 0) ? W1 : (seg == 1) ? W2 : W3a;
        const float* Wb = (seg == 2) ? W3b : nullptr;

        for (int k0 = 0; k0 < K; k0 += BK) {
            // load A tile (BM x BK), store transposed As[k][m]
#pragma unroll
            for (int l = 0; l < 2; l++) {
                int slot = tid * 2 + l;      // 0..511 float4 slots
                int row = slot >> 2;         // 0..127
                int c4 = slot & 3;           // which float4 in the 16-wide k
                int gr = m0 + row;
                float4 v = make_float4(0.f, 0.f, 0.f, 0.f);
                if (gr < N_NODES)
                    v = *reinterpret_cast<const float4*>(A + (size_t)gr * K + k0 + c4 * 4);
                As[c4 * 4 + 0][row] = v.x;
                As[c4 * 4 + 1][row] = v.y;
                As[c4 * 4 + 2][row] = v.z;
                As[c4 * 4 + 3][row] = v.w;
            }
            // load B tile (BK x BN): 1 float4 per thread
            {
                int kr = tid >> 4;   // 0..15
                int nc = tid & 15;   // 0..15 -> 4 cols
                const float* wp = W + (size_t)(k0 + kr) * HID + n0 + nc * 4;
                float4 v = *reinterpret_cast<const float4*>(wp);
                if (Wb) {
                    const float* wq = Wb + (size_t)(k0 + kr) * HID + n0 + nc * 4;
                    float4 u = *reinterpret_cast<const float4*>(wq);
                    v.x += u.x; v.y += u.y; v.z += u.z; v.w += u.w;
                }
                *reinterpret_cast<float4*>(&Bs[kr][nc * 4]) = v;
            }
            __syncthreads();
#pragma unroll
            for (int k = 0; k < BK; k++) {
                float4 va0 = *reinterpret_cast<const float4*>(&As[k][ty * 8]);
                float4 va1 = *reinterpret_cast<const float4*>(&As[k][ty * 8 + 4]);
                float4 vb  = *reinterpret_cast<const float4*>(&Bs[k][tx * 4]);
                float a[8] = {va0.x, va0.y, va0.z, va0.w, va1.x, va1.y, va1.z, va1.w};
                float b[4] = {vb.x, vb.y, vb.z, vb.w};
#pragma unroll
                for (int i = 0; i < 8; i++)
#pragma unroll
                    for (int j = 0; j < 4; j++) acc[i][j] += a[i] * b[j];
            }
            __syncthreads();
        }
    }
    // epilogue: bias
#pragma unroll
    for (int i = 0; i < 8; i++) {
        int gr = m0 + ty * 8 + i;
        if (gr < N_NODES) {
#pragma unroll
            for (int j = 0; j < 4; j++) {
                int gc = n0 + tx * 4 + j;
                C[(size_t)gr * HID + gc] = acc[i][j] + ba[gc] + bb[gc];
            }
        }
    }
}

// ---------------- batchnorm ---------------------------------------------------
__global__ void k_zero_stats(float* __restrict__ out) {
    int i = threadIdx.x + blockIdx.x * blockDim.x;
    if (i < 2 * HID) g_stats[i] = 0.f;
    if (i < HID) out[i] = 0.f;   // relu output >= 0, so 0 is the identity for max
}

#define ROWS_PER_BLK 128

__global__ void k_bnstats(int layer) {
    const float* h = layer ? g_h2 : g_h1;
    int col = threadIdx.x;
    int r0 = blockIdx.x * ROWS_PER_BLK;
    int rend = r0 + ROWS_PER_BLK;
    if (rend > N_NODES) rend = N_NODES;
    float s = 0.f, ss = 0.f;
    for (int r = r0; r < rend; r++) {
        float v = h[(size_t)r * HID + col];
        s += v; ss += v * v;
    }
    atomicAdd(&g_stats[col], s);
    atomicAdd(&g_stats[HID + col], ss);
}

__global__ void k_bnapply(const float* __restrict__ g, const float* __restrict__ beta) {
    int col = threadIdx.x;
    float mu = g_stats[col] * (1.0f / N_NODES);
    float var = g_stats[HID + col] * (1.0f / N_NODES) - mu * mu;
    float sc = g[col] * rsqrtf(var + BN_EPS);
    float sh = beta[col] - mu * sc;
    int r0 = blockIdx.x * ROWS_PER_BLK;
    int rend = r0 + ROWS_PER_BLK;
    if (rend > N_NODES) rend = N_NODES;
    for (int r = r0; r < rend; r++) {
        size_t idx = (size_t)r * HID + col;
        float v = g_h1[idx] * sc + sh;
        g_h1[idx] = v > 0.f ? v : 0.f;
    }
}

__global__ void k_bnapply_max(const float* __restrict__ g, const float* __restrict__ beta,
                              float* __restrict__ out) {
    int col = threadIdx.x;
    float mu = g_stats[col] * (1.0f / N_NODES);
    float var = g_stats[HID + col] * (1.0f / N_NODES) - mu * mu;
    float sc = g[col] * rsqrtf(var + BN_EPS);
    float sh = beta[col] - mu * sc;
    int r0 = blockIdx.x * ROWS_PER_BLK;
    int rend = r0 + ROWS_PER_BLK;
    if (rend > N_NODES) rend = N_NODES;
    float mx = 0.f;
    for (int r = r0; r < rend; r++) {
        float v = g_h2[(size_t)r * HID + col] * sc + sh;
        v = v > 0.f ? v : 0.f;
        if (v > mx) mx = v;
    }
    // values are >= 0: IEEE bits compare monotonically as signed ints
    atomicMax(reinterpret_cast<int*>(out) + col, __float_as_int(mx));
}

// ---------------- launch ------------------------------------------------------
extern "C" void kernel_launch(void* const* d_in, const int* in_sizes, int n_in,
                              void* d_out, int out_size) {
    const float* x     = (const float*)d_in[0];
    const int*   ei32  = (const int*)d_in[1];   // int32 or int64 (detected)
    const float* Wl_f1 = (const float*)d_in[2];
    const float* bl_f1 = (const float*)d_in[3];
    const float* Wr_f1 = (const float*)d_in[4];
    const float* Wl_b1 = (const float*)d_in[5];
    const float* bl_b1 = (const float*)d_in[6];
    const float* Wr_b1 = (const float*)d_in[7];
    const float* Wl_f2 = (const float*)d_in[8];
    const float* bl_f2 = (const float*)d_in[9];
    const float* Wr_f2 = (const float*)d_in[10];
    const float* Wl_b2 = (const float*)d_in[11];
    const float* bl_b2 = (const float*)d_in[12];
    const float* Wr_b2 = (const float*)d_in[13];
    const float* g1    = (const float*)d_in[14];
    const float* beta1 = (const float*)d_in[15];
    const float* g2    = (const float*)d_in[16];
    const float* beta2 = (const float*)d_in[17];
    float* out = (float*)d_out;

    // ---- build CSR (shared by both layers) ----
    k_detect<<<1, 32>>>(ei32);
    k_zero_deg<<<(N_NODES + 1023) / 1024, 1024>>>();
    k_count<<<(N_EDGES + 255) / 256, 256>>>(ei32);
    k_scan<<<1, 1024>>>();
    k_scatter<<<(N_EDGES + 255) / 256, 256>>>(ei32);

    const int aggBlocks = (N_NODES + 7) / 8;   // 8 warps/block, 1 warp/node
    dim3 gemmGrid((N_NODES + BM - 1) / BM, HID / BN);

    // ---- layer 1 ----
    k_agg<D_IN><<<aggBlocks, 256>>>(x, 0, 0);
    k_agg<D_IN><<<aggBlocks, 256>>>(x, 1, 0);
    k_gemm3<<<gemmGrid, 256>>>(x, Wl_f1, Wl_b1, Wr_f1, Wr_b1, bl_f1, bl_b1, D_IN, 0);
    k_zero_stats<<<1, 512>>>(out);
    k_bnstats<<<(N_NODES + ROWS_PER_BLK - 1) / ROWS_PER_BLK, HID>>>(0);
    k_bnapply<<<(N_NODES + ROWS_PER_BLK - 1) / ROWS_PER_BLK, HID>>>(g1, beta1);

    // ---- layer 2 ----
    k_agg<HID><<<aggBlocks, 256>>>(x, 0, 1);
    k_agg<HID><<<aggBlocks, 256>>>(x, 1, 1);
    k_gemm3<<<gemmGrid, 256>>>(x, Wl_f2, Wl_b2, Wr_f2, Wr_b2, bl_f2, bl_b2, HID, 1);
    k_zero_stats<<<1, 512>>>(out);
    k_bnstats<<<(N_NODES + ROWS_PER_BLK - 1) / ROWS_PER_BLK, HID>>>(1);
    k_bnapply_max<<<(N_NODES + ROWS_PER_BLK - 1) / ROWS_PER_BLK, HID>>>(g2, beta2, out);

    (void)in_sizes; (void)n_in; (void)out_size;
}

// round 4
// speedup vs baseline: 1.4272x; 1.4272x over previous
#include <cuda_runtime.h>
#include <cuda_bf16.h>
#include <cstdint>

#define N_NODES 50000
#define N_EDGES 400000
#define D_IN    128
#define HID     256
#define BN_EPS  1e-5f

// ---------------- scratch (static __device__ globals) -------------------------
__device__ int   g_is64;
__device__ int   g_deg_f[N_NODES];
__device__ int   g_deg_b[N_NODES];
__device__ int   g_off_f[N_NODES + 1];
__device__ int   g_off_b[N_NODES + 1];
__device__ int   g_cur_f[N_NODES];
__device__ int   g_cur_b[N_NODES];
__device__ int   g_adj_f[N_EDGES];
__device__ int   g_adj_b[N_EDGES];
__device__ __align__(16) float g_mean_f[(size_t)N_NODES * HID];
__device__ __align__(16) float g_mean_b[(size_t)N_NODES * HID];
__device__ __align__(16) float g_h1[(size_t)N_NODES * HID];   // raw (pre-BN)
__device__ __align__(16) float g_h2[(size_t)N_NODES * HID];   // raw (pre-BN)
__device__ float g_stats[2 * HID];
__device__ __align__(16) float g_sc[HID];
__device__ __align__(16) float g_sh[HID];
// prepped weights: bf16 hi/lo, layout [seg][k][256] row-major
__device__ __align__(16) __nv_bfloat16 g_Wh1[3 * 128 * 256];
__device__ __align__(16) __nv_bfloat16 g_Wl1[3 * 128 * 256];
__device__ __align__(16) __nv_bfloat16 g_Wh2[3 * 256 * 256];
__device__ __align__(16) __nv_bfloat16 g_Wl2[3 * 256 * 256];

// ---------------- helpers -------------------------------------------------------
__device__ __forceinline__ uint32_t smem_u32(const void* p) {
    uint32_t a;
    asm("{ .reg .u64 t; cvta.to.shared.u64 t, %1; cvt.u32.u64 %0, t; }" : "=r"(a) : "l"(p));
    return a;
}
__device__ __forceinline__ void ldsm4(uint32_t addr, uint32_t& r0, uint32_t& r1,
                                      uint32_t& r2, uint32_t& r3) {
    asm volatile("ldmatrix.sync.aligned.m8n8.x4.shared.b16 {%0,%1,%2,%3}, [%4];"
                 : "=r"(r0), "=r"(r1), "=r"(r2), "=r"(r3) : "r"(addr));
}
__device__ __forceinline__ void ldsm4t(uint32_t addr, uint32_t& r0, uint32_t& r1,
                                       uint32_t& r2, uint32_t& r3) {
    asm volatile("ldmatrix.sync.aligned.m8n8.x4.trans.shared.b16 {%0,%1,%2,%3}, [%4];"
                 : "=r"(r0), "=r"(r1), "=r"(r2), "=r"(r3) : "r"(addr));
}
__device__ __forceinline__ void mma_bf16(float* c, const uint32_t* a, const uint32_t* b) {
    asm volatile(
        "mma.sync.aligned.m16n8k16.row.col.f32.bf16.bf16.f32 "
        "{%0,%1,%2,%3}, {%4,%5,%6,%7}, {%8,%9}, {%0,%1,%2,%3};"
        : "+f"(c[0]), "+f"(c[1]), "+f"(c[2]), "+f"(c[3])
        : "r"(a[0]), "r"(a[1]), "r"(a[2]), "r"(a[3]), "r"(b[0]), "r"(b[1]));
}
__device__ __forceinline__ void split2(float a, float b, uint32_t& hi, uint32_t& lo) {
    __nv_bfloat16 ha = __float2bfloat16_rn(a), hb = __float2bfloat16_rn(b);
    __nv_bfloat16 la = __float2bfloat16_rn(a - __bfloat162float(ha));
    __nv_bfloat16 lb = __float2bfloat16_rn(b - __bfloat162float(hb));
    hi = (uint32_t)__bfloat16_as_ushort(ha) | ((uint32_t)__bfloat16_as_ushort(hb) << 16);
    lo = (uint32_t)__bfloat16_as_ushort(la) | ((uint32_t)__bfloat16_as_ushort(lb) << 16);
}

// ---------------- edge dtype detection (parallel) ------------------------------
__global__ void k_detect(const int* __restrict__ ei32) {
    int t = threadIdx.x;
    int nz = (ei32[2 * t + 1] != 0) ? 1 : 0;
    int any = __syncthreads_or(nz);
    if (t == 0) g_is64 = any ? 0 : 1;
}
__device__ __forceinline__ void load_edge(const int* ei32, int i, int& s, int& d) {
    if (g_is64) { s = ei32[2 * i]; d = ei32[2 * (N_EDGES + i)]; }
    else        { s = ei32[i];     d = ei32[N_EDGES + i]; }
}

// ---------------- graph build ---------------------------------------------------
__global__ void k_zero_deg() {
    int i = blockIdx.x * blockDim.x + threadIdx.x;
    if (i < N_NODES) { g_deg_f[i] = 0; g_deg_b[i] = 0; }
}
__global__ void k_count(const int* __restrict__ ei32) {
    int i = blockIdx.x * blockDim.x + threadIdx.x;
    if (i < N_EDGES) {
        int s, d; load_edge(ei32, i, s, d);
        if ((unsigned)s < N_NODES && (unsigned)d < N_NODES) {
            atomicAdd(&g_deg_b[s], 1);
            atomicAdd(&g_deg_f[d], 1);
        }
    }
}
// fast single-block scan: each thread owns a 49-element chunk
__global__ void k_scan2() {
    __shared__ int wsum[32];
    const int T = 1024;
    const int CH = (N_NODES + T - 1) / T;   // 49
    int t = threadIdx.x, lane = t & 31, w = t >> 5;
    for (int pass = 0; pass < 2; pass++) {
        const int* deg = pass ? g_deg_b : g_deg_f;
        int* off = pass ? g_off_b : g_off_f;
        int* cur = pass ? g_cur_b : g_cur_f;
        int lo = t * CH;
        int hi = lo + CH; if (hi > N_NODES) hi = N_NODES;
        int s = 0;
        for (int i = lo; i < hi; i++) s += deg[i];
        int v = s;
        #pragma unroll
        for (int o = 1; o < 32; o <<= 1) {
            int u = __shfl_up_sync(0xFFFFFFFFu, v, o);
            if (lane >= o) v += u;
        }
        if (lane == 31) wsum[w] = v;
        __syncthreads();
        if (w == 0) {
            int z = wsum[lane];
            #pragma unroll
            for (int o = 1; o < 32; o <<= 1) {
                int u = __shfl_up_sync(0xFFFFFFFFu, z, o);
                if (lane >= o) z += u;
            }
            wsum[lane] = z;
        }
        __syncthreads();
        int ex = v - s + (w > 0 ? wsum[w - 1] : 0);
        int run = ex;
        for (int i = lo; i < hi; i++) { off[i] = run; cur[i] = run; run += deg[i]; }
        if (t == 0) off[N_NODES] = wsum[31];
        __syncthreads();
    }
}
__global__ void k_scatter(const int* __restrict__ ei32) {
    int i = blockIdx.x * blockDim.x + threadIdx.x;
    if (i < N_EDGES) {
        int s, d; load_edge(ei32, i, s, d);
        if ((unsigned)s < N_NODES && (unsigned)d < N_NODES) {
            int p = atomicAdd(&g_cur_f[d], 1); g_adj_f[p] = s;
            int q = atomicAdd(&g_cur_b[s], 1); g_adj_b[q] = d;
        }
    }
}

// ---------------- aggregation: one warp per node --------------------------------
template <int D>
__global__ void k_agg(const float* __restrict__ x, int dir, int affine) {
    int warp = (blockIdx.x * blockDim.x + threadIdx.x) >> 5;
    int lane = threadIdx.x & 31;
    if (warp >= N_NODES) return;
    const float* feat = affine ? g_h1 : x;
    const int* off = dir ? g_off_b : g_off_f;
    const int* adj = dir ? g_adj_b : g_adj_f;
    float* out = dir ? g_mean_b : g_mean_f;

    float4 sc0, sh0, sc1, sh1;
    if (affine) {
        sc0 = *reinterpret_cast<const float4*>(g_sc + 4 * lane);
        sh0 = *reinterpret_cast<const float4*>(g_sh + 4 * lane);
        if (D == 256) {
            sc1 = *reinterpret_cast<const float4*>(g_sc + 128 + 4 * lane);
            sh1 = *reinterpret_cast<const float4*>(g_sh + 128 + 4 * lane);
        }
    }
    int s = off[warp], e = off[warp + 1];
    float4 a0 = make_float4(0.f, 0.f, 0.f, 0.f);
    float4 a1 = make_float4(0.f, 0.f, 0.f, 0.f);
    for (int j = s; j < e; j++) {
        int nb = adj[j];
        const float4* p = reinterpret_cast<const float4*>(feat + (size_t)nb * D);
        float4 v = p[lane];
        if (affine) {
            v.x = fmaxf(v.x * sc0.x + sh0.x, 0.f);
            v.y = fmaxf(v.y * sc0.y + sh0.y, 0.f);
            v.z = fmaxf(v.z * sc0.z + sh0.z, 0.f);
            v.w = fmaxf(v.w * sc0.w + sh0.w, 0.f);
        }
        a0.x += v.x; a0.y += v.y; a0.z += v.z; a0.w += v.w;
        if (D == 256) {
            float4 u = p[lane + 32];
            if (affine) {
                u.x = fmaxf(u.x * sc1.x + sh1.x, 0.f);
                u.y = fmaxf(u.y * sc1.y + sh1.y, 0.f);
                u.z = fmaxf(u.z * sc1.z + sh1.z, 0.f);
                u.w = fmaxf(u.w * sc1.w + sh1.w, 0.f);
            }
            a1.x += u.x; a1.y += u.y; a1.z += u.z; a1.w += u.w;
        }
    }
    int cnt = e - s;
    float inv = 1.0f / (float)(cnt > 0 ? cnt : 1);
    a0.x *= inv; a0.y *= inv; a0.z *= inv; a0.w *= inv;
    float4* q = reinterpret_cast<float4*>(out + (size_t)warp * D);
    q[lane] = a0;
    if (D == 256) {
        a1.x *= inv; a1.y *= inv; a1.z *= inv; a1.w *= inv;
        q[lane + 32] = a1;
    }
}

// ---------------- weight prep: fp32 [K,256] -> hi/lo bf16 [seg][k][256] --------
__global__ void k_prepW(const float* __restrict__ W1, const float* __restrict__ W2,
                        const float* __restrict__ W3a, const float* __restrict__ W3b,
                        int layer) {
    int K = layer ? 256 : 128;
    int seg = blockIdx.x / K;
    int k = blockIdx.x % K;
    const float* W  = seg == 0 ? W1 : seg == 1 ? W2 : W3a;
    const float* Wb = seg == 2 ? W3b : nullptr;
    __nv_bfloat16* Wh = layer ? g_Wh2 : g_Wh1;
    __nv_bfloat16* Wl = layer ? g_Wl2 : g_Wl1;
    int n = threadIdx.x;
    float v = W[(size_t)k * HID + n];
    if (Wb) v += Wb[(size_t)k * HID + n];
    __nv_bfloat16 h = __float2bfloat16_rn(v);
    __nv_bfloat16 l = __float2bfloat16_rn(v - __bfloat162float(h));
    size_t idx = (size_t)(seg * K + k) * HID + n;
    Wh[idx] = h;
    Wl[idx] = l;
}

// ---------------- mma.sync GEMM: C[64-tile, 128-tile] = sum_seg A_seg@B_seg + bias
// hi/lo bf16 split: AhBh + AhBl + AlBh accumulated in fp32.
#define BM 64
#define BN 128
#define BK 32
#define A_STR 40
#define B_STR 136

__global__ __launch_bounds__(256)
void k_gemm_mma(const float* __restrict__ xin,
                const float* __restrict__ ba, const float* __restrict__ bb,
                int layer) {
    __shared__ __align__(16) __nv_bfloat16 sAh[BM][A_STR];
    __shared__ __align__(16) __nv_bfloat16 sAl[BM][A_STR];
    __shared__ __align__(16) __nv_bfloat16 sBh[BK][B_STR];
    __shared__ __align__(16) __nv_bfloat16 sBl[BK][B_STR];
    __shared__ float sBias[BN];
    __shared__ float sSc[HID];
    __shared__ float sSh[HID];

    const int K = layer ? 256 : 128;
    int tid = threadIdx.x;
    int wid = tid >> 5, lane = tid & 31;
    int m0 = blockIdx.x * BM;
    int n0b = blockIdx.y * BN;
    int wm = wid >> 2;          // 0..1 (32 rows each)
    int wn = wid & 3;           // 0..3 (32 cols each)

    if (tid < BN) sBias[tid] = ba[n0b + tid] + bb[n0b + tid];
    if (layer) {
        if (tid < HID) { sSc[tid] = g_sc[tid]; sSh[tid] = g_sh[tid]; }
    }

    const __nv_bfloat16* Wh = layer ? g_Wh2 : g_Wh1;
    const __nv_bfloat16* Wl = layer ? g_Wl2 : g_Wl1;

    uint32_t ahBase = smem_u32(&sAh[0][0]);
    uint32_t alBase = smem_u32(&sAl[0][0]);
    uint32_t bhBase = smem_u32(&sBh[0][0]);
    uint32_t blBase = smem_u32(&sBl[0][0]);

    float acc[2][4][4];
#pragma unroll
    for (int i = 0; i < 2; i++)
#pragma unroll
        for (int j = 0; j < 4; j++)
#pragma unroll
            for (int q = 0; q < 4; q++) acc[i][j][q] = 0.f;

    // A-fill indices: row = tid>>2 (0..63), colgrp = tid&3 (8 cols)
    int aRow = tid >> 2, aCg = tid & 3;
    // B-fill indices: krow = tid>>3 (0..31), ncol = (tid&7)*16
    int bK = tid >> 3, bN = (tid & 7) * 16;

    for (int seg = 0; seg < 3; seg++) {
        const float* A = seg == 0 ? g_mean_f : seg == 1 ? g_mean_b : (layer ? g_h1 : xin);
        bool doAff = (seg == 2 && layer);
        for (int k0 = 0; k0 < K; k0 += BK) {
            __syncthreads();
            // ---- A chunk -> hi/lo bf16 smem
            {
                int gr = m0 + aRow;
                float4 v0 = make_float4(0.f, 0.f, 0.f, 0.f);
                float4 v1 = v0;
                if (gr < N_NODES) {
                    const float* src = A + (size_t)gr * K + k0 + aCg * 8;
                    v0 = *reinterpret_cast<const float4*>(src);
                    v1 = *reinterpret_cast<const float4*>(src + 4);
                }
                if (doAff) {
                    int cb = k0 + aCg * 8;
                    v0.x = fmaxf(v0.x * sSc[cb]     + sSh[cb],     0.f);
                    v0.y = fmaxf(v0.y * sSc[cb + 1] + sSh[cb + 1], 0.f);
                    v0.z = fmaxf(v0.z * sSc[cb + 2] + sSh[cb + 2], 0.f);
                    v0.w = fmaxf(v0.w * sSc[cb + 3] + sSh[cb + 3], 0.f);
                    v1.x = fmaxf(v1.x * sSc[cb + 4] + sSh[cb + 4], 0.f);
                    v1.y = fmaxf(v1.y * sSc[cb + 5] + sSh[cb + 5], 0.f);
                    v1.z = fmaxf(v1.z * sSc[cb + 6] + sSh[cb + 6], 0.f);
                    v1.w = fmaxf(v1.w * sSc[cb + 7] + sSh[cb + 7], 0.f);
                }
                uint4 uh, ul;
                split2(v0.x, v0.y, uh.x, ul.x);
                split2(v0.z, v0.w, uh.y, ul.y);
                split2(v1.x, v1.y, uh.z, ul.z);
                split2(v1.z, v1.w, uh.w, ul.w);
                *reinterpret_cast<uint4*>(&sAh[aRow][aCg * 8]) = uh;
                *reinterpret_cast<uint4*>(&sAl[aRow][aCg * 8]) = ul;
            }
            // ---- B chunk: straight copies of prepped bf16
            {
                size_t gidx = (size_t)(seg * K + k0 + bK) * HID + n0b + bN;
                const uint4* sh0 = reinterpret_cast<const uint4*>(Wh + gidx);
                const uint4* sl0 = reinterpret_cast<const uint4*>(Wl + gidx);
                *reinterpret_cast<uint4*>(&sBh[bK][bN])     = sh0[0];
                *reinterpret_cast<uint4*>(&sBh[bK][bN + 8]) = sh0[1];
                *reinterpret_cast<uint4*>(&sBl[bK][bN])     = sl0[0];
                *reinterpret_cast<uint4*>(&sBl[bK][bN + 8]) = sl0[1];
            }
            __syncthreads();
            // ---- MMA over 2 k-steps of 16
#pragma unroll
            for (int ks = 0; ks < 2; ks++) {
                uint32_t ah[2][4], al[2][4], bh[4][2], bl[4][2];
#pragma unroll
                for (int mf = 0; mf < 2; mf++) {
                    uint32_t off = ((wm * 32 + mf * 16 + (lane & 15)) * A_STR
                                    + ks * 16 + (lane >> 4) * 8) * 2;
                    ldsm4(ahBase + off, ah[mf][0], ah[mf][1], ah[mf][2], ah[mf][3]);
                    ldsm4(alBase + off, al[mf][0], al[mf][1], al[mf][2], al[mf][3]);
                }
#pragma unroll
                for (int np = 0; np < 2; np++) {
                    uint32_t off = ((ks * 16 + (lane & 15)) * B_STR
                                    + wn * 32 + np * 16 + (lane >> 4) * 8) * 2;
                    ldsm4t(bhBase + off, bh[np * 2][0], bh[np * 2][1],
                           bh[np * 2 + 1][0], bh[np * 2 + 1][1]);
                    ldsm4t(blBase + off, bl[np * 2][0], bl[np * 2][1],
                           bl[np * 2 + 1][0], bl[np * 2 + 1][1]);
                }
#pragma unroll
                for (int mf = 0; mf < 2; mf++)
#pragma unroll
                    for (int nf = 0; nf < 4; nf++) {
                        mma_bf16(acc[mf][nf], ah[mf], bh[nf]);
                        mma_bf16(acc[mf][nf], ah[mf], bl[nf]);
                        mma_bf16(acc[mf][nf], al[mf], bh[nf]);
                    }
            }
        }
    }

    // ---- epilogue: bias + store fp32
    float* C = layer ? g_h2 : g_h1;
#pragma unroll
    for (int mf = 0; mf < 2; mf++) {
#pragma unroll
        for (int nf = 0; nf < 4; nf++) {
            int row = m0 + wm * 32 + mf * 16 + (lane >> 2);
            int cl = wn * 32 + nf * 8 + (lane & 3) * 2;
            float b0 = sBias[cl], b1 = sBias[cl + 1];
            if (row < N_NODES) {
                float2 v = make_float2(acc[mf][nf][0] + b0, acc[mf][nf][1] + b1);
                *reinterpret_cast<float2*>(C + (size_t)row * HID + n0b + cl) = v;
            }
            if (row + 8 < N_NODES) {
                float2 v = make_float2(acc[mf][nf][2] + b0, acc[mf][nf][3] + b1);
                *reinterpret_cast<float2*>(C + (size_t)(row + 8) * HID + n0b + cl) = v;
            }
        }
    }
}

// ---------------- batchnorm stats / finalize / max ------------------------------
__global__ void k_zero_stats(float* __restrict__ out) {
    int i = threadIdx.x + blockIdx.x * blockDim.x;
    if (i < 2 * HID) g_stats[i] = 0.f;
    if (i < HID) out[i] = 0.f;
}
#define ROWS_PER_BLK 128
__global__ void k_bnstats(int layer) {
    const float* h = layer ? g_h2 : g_h1;
    int col = threadIdx.x;
    int r0 = blockIdx.x * ROWS_PER_BLK;
    int rend = r0 + ROWS_PER_BLK; if (rend > N_NODES) rend = N_NODES;
    float s = 0.f, ss = 0.f;
    for (int r = r0; r < rend; r++) {
        float v = h[(size_t)r * HID + col];
        s += v; ss += v * v;
    }
    atomicAdd(&g_stats[col], s);
    atomicAdd(&g_stats[HID + col], ss);
}
__global__ void k_bnfinal(const float* __restrict__ g, const float* __restrict__ beta) {
    int c = threadIdx.x;
    float mu = g_stats[c] * (1.0f / N_NODES);
    float var = g_stats[HID + c] * (1.0f / N_NODES) - mu * mu;
    float sc = g[c] * rsqrtf(var + BN_EPS);
    g_sc[c] = sc;
    g_sh[c] = beta[c] - mu * sc;
}
__global__ void k_max(float* __restrict__ out) {
    int col = threadIdx.x;
    float sc = g_sc[col], sh = g_sh[col];
    int r0 = blockIdx.x * ROWS_PER_BLK;
    int rend = r0 + ROWS_PER_BLK; if (rend > N_NODES) rend = N_NODES;
    float mx = 0.f;
    for (int r = r0; r < rend; r++) {
        float v = fmaxf(g_h2[(size_t)r * HID + col] * sc + sh, 0.f);
        if (v > mx) mx = v;
    }
    atomicMax(reinterpret_cast<int*>(out) + col, __float_as_int(mx));
}

// ---------------- launch ----------------------------------------------------------
extern "C" void kernel_launch(void* const* d_in, const int* in_sizes, int n_in,
                              void* d_out, int out_size) {
    const float* x     = (const float*)d_in[0];
    const int*   ei32  = (const int*)d_in[1];
    const float* Wl_f1 = (const float*)d_in[2];
    const float* bl_f1 = (const float*)d_in[3];
    const float* Wr_f1 = (const float*)d_in[4];
    const float* Wl_b1 = (const float*)d_in[5];
    const float* bl_b1 = (const float*)d_in[6];
    const float* Wr_b1 = (const float*)d_in[7];
    const float* Wl_f2 = (const float*)d_in[8];
    const float* bl_f2 = (const float*)d_in[9];
    const float* Wr_f2 = (const float*)d_in[10];
    const float* Wl_b2 = (const float*)d_in[11];
    const float* bl_b2 = (const float*)d_in[12];
    const float* Wr_b2 = (const float*)d_in[13];
    const float* g1    = (const float*)d_in[14];
    const float* beta1 = (const float*)d_in[15];
    const float* g2    = (const float*)d_in[16];
    const float* beta2 = (const float*)d_in[17];
    float* out = (float*)d_out;

    // ---- CSR build ----
    k_detect<<<1, 256>>>(ei32);
    k_zero_deg<<<(N_NODES + 1023) / 1024, 1024>>>();
    k_count<<<(N_EDGES + 255) / 256, 256>>>(ei32);
    k_scan2<<<1, 1024>>>();
    k_scatter<<<(N_EDGES + 255) / 256, 256>>>(ei32);

    // ---- weight prep (one block per (seg,k) row) ----
    k_prepW<<<3 * 128, 256>>>(Wl_f1, Wl_b1, Wr_f1, Wr_b1, 0);
    k_prepW<<<3 * 256, 256>>>(Wl_f2, Wl_b2, Wr_f2, Wr_b2, 1);

    const int aggBlocks = (N_NODES + 7) / 8;
    dim3 gemmGrid((N_NODES + BM - 1) / BM, HID / BN);   // (782, 2)
    const int bnBlocks = (N_NODES + ROWS_PER_BLK - 1) / ROWS_PER_BLK;

    // ---- layer 1 ----
    k_agg<D_IN><<<aggBlocks, 256>>>(x, 0, 0);
    k_agg<D_IN><<<aggBlocks, 256>>>(x, 1, 0);
    k_gemm_mma<<<gemmGrid, 256>>>(x, bl_f1, bl_b1, 0);
    k_zero_stats<<<1, 512>>>(out);
    k_bnstats<<<bnBlocks, HID>>>(0);
    k_bnfinal<<<1, HID>>>(g1, beta1);

    // ---- layer 2 (affine+relu applied on the fly from raw h1) ----
    k_agg<HID><<<aggBlocks, 256>>>(x, 0, 1);
    k_agg<HID><<<aggBlocks, 256>>>(x, 1, 1);
    k_gemm_mma<<<gemmGrid, 256>>>(x, bl_f2, bl_b2, 1);
    k_zero_stats<<<1, 512>>>(out);
    k_bnstats<<<bnBlocks, HID>>>(1);
    k_bnfinal<<<1, HID>>>(g2, beta2);
    k_max<<<bnBlocks, HID>>>(out);

    (void)in_sizes; (void)n_in; (void)out_size;
}